// round 2
// baseline (speedup 1.0000x reference)
#include <cuda_runtime.h>
#include <math.h>
#include <limits.h>

#define BB 8
#define HH 256
#define WW 256
#define KK 100
#define JJ 17
#define HW (HH*WW)
#define MAXC 16384
#define THRESH_F 0.1f

// ---------------- scratch (device globals; no allocation allowed) ----------------
__device__ float g_top_scores[BB][KK];
__device__ int   g_top_inds[BB][KK];
__device__ float g_hm_scores[BB][JJ][KK];
__device__ int   g_hm_inds[BB][JJ][KK];
__device__ float g_bboxes[BB][KK][4];

// ---------------- elementwise sigmoid (vectorized) ----------------
__global__ void sigmoid_kernel(const float4* __restrict__ in, float4* __restrict__ out, int n4) {
    int i = blockIdx.x * blockDim.x + threadIdx.x;
    if (i < n4) {
        float4 v = in[i];
        v.x = 1.0f / (1.0f + expf(-v.x));
        v.y = 1.0f / (1.0f + expf(-v.y));
        v.z = 1.0f / (1.0f + expf(-v.z));
        v.w = 1.0f / (1.0f + expf(-v.w));
        out[i] = v;
    }
}

// ---------------- fused NMS + top-K per channel ----------------
// blockIdx.x in [0, BB + BB*JJ): first BB blocks handle hm channels (one per batch),
// remaining handle hm_hp channels (b-major, j-minor: e = b*JJ + j).
// Reads the SIGMOID values already written to d_out (exact reference tie semantics).
__global__ void topk_kernel(const float* __restrict__ out_hm, const float* __restrict__ out_hmhp) {
    extern __shared__ char smem_raw[];
    float* cvals = (float*)smem_raw;            // MAXC
    int*   cinds = (int*)(cvals + MAXC);        // MAXC
    __shared__ int s_count;
    __shared__ float s_rv[32];
    __shared__ int   s_ri[32];
    __shared__ int   s_rp[32];

    int ch = blockIdx.x;
    const float* src = (ch < BB) ? (out_hm + (long)ch * HW)
                                 : (out_hmhp + (long)(ch - BB) * HW);

    if (threadIdx.x == 0) s_count = 0;
    __syncthreads();

    // Phase 1: 3x3 NMS + candidate collection
    for (int p = threadIdx.x; p < HW; p += blockDim.x) {
        float v = src[p];
        int x = p & (WW - 1);
        int y = p >> 8;
        bool ismax;
        if (x > 0 && x < WW - 1 && y > 0 && y < HH - 1) {
            ismax =  v >= src[p - WW - 1] && v >= src[p - WW] && v >= src[p - WW + 1]
                  && v >= src[p - 1]      && v >= src[p + 1]
                  && v >= src[p + WW - 1] && v >= src[p + WW] && v >= src[p + WW + 1];
        } else {
            ismax = true;
            #pragma unroll
            for (int dy = -1; dy <= 1; dy++) {
                #pragma unroll
                for (int dx = -1; dx <= 1; dx++) {
                    if (dy == 0 && dx == 0) continue;
                    int yy = y + dy, xx = x + dx;
                    if (yy >= 0 && yy < HH && xx >= 0 && xx < WW)
                        ismax = ismax && (v >= src[yy * WW + xx]);
                }
            }
        }
        if (ismax) {
            int pos = atomicAdd(&s_count, 1);
            if (pos < MAXC) { cvals[pos] = v; cinds[pos] = p; }
        }
    }
    __syncthreads();
    int count = min(s_count, MAXC);

    // Phase 2: K iterations of block-wide argmax extraction.
    // Tie-break: equal value -> lower pixel index first (matches jax.lax.top_k).
    for (int k = 0; k < KK; k++) {
        float bv = -1e30f; int bi = INT_MAX; int bp = -1;
        for (int c = threadIdx.x; c < count; c += blockDim.x) {
            float v = cvals[c];
            int pi = cinds[c];
            if (v > bv || (v == bv && pi < bi)) { bv = v; bi = pi; bp = c; }
        }
        // warp reduce
        #pragma unroll
        for (int off = 16; off > 0; off >>= 1) {
            float ov = __shfl_down_sync(0xffffffffu, bv, off);
            int   oi = __shfl_down_sync(0xffffffffu, bi, off);
            int   op = __shfl_down_sync(0xffffffffu, bp, off);
            if (ov > bv || (ov == bv && oi < bi)) { bv = ov; bi = oi; bp = op; }
        }
        int wid = threadIdx.x >> 5, lane = threadIdx.x & 31;
        if (lane == 0) { s_rv[wid] = bv; s_ri[wid] = bi; s_rp[wid] = bp; }
        __syncthreads();
        if (wid == 0) {
            int nw = blockDim.x >> 5;
            bv = (lane < nw) ? s_rv[lane] : -1e30f;
            bi = (lane < nw) ? s_ri[lane] : INT_MAX;
            bp = (lane < nw) ? s_rp[lane] : -1;
            #pragma unroll
            for (int off = 16; off > 0; off >>= 1) {
                float ov = __shfl_down_sync(0xffffffffu, bv, off);
                int   oi = __shfl_down_sync(0xffffffffu, bi, off);
                int   op = __shfl_down_sync(0xffffffffu, bp, off);
                if (ov > bv || (ov == bv && oi < bi)) { bv = ov; bi = oi; bp = op; }
            }
            if (lane == 0) {
                float outv = 0.0f; int outi = 0;
                if (bp >= 0) { cvals[bp] = -1e30f; outv = bv; outi = bi; }
                if (ch < BB) {
                    g_top_scores[ch][k] = outv;
                    g_top_inds[ch][k]   = outi;
                } else {
                    int e = ch - BB;
                    g_hm_scores[e / JJ][e % JJ][k] = outv;
                    g_hm_inds[e / JJ][e % JJ][k]   = outi;
                }
            }
        }
        __syncthreads();
    }
}

// ---------------- bbox + score + class columns ----------------
__global__ void bbox_kernel(const float* __restrict__ reg, const float* __restrict__ wh,
                            float* __restrict__ det) {
    int b = blockIdx.x;
    int k = threadIdx.x;
    if (k >= KK) return;
    int ind = g_top_inds[b][k];
    float score = g_top_scores[b][k];
    float x0 = (float)(ind & (WW - 1));
    float y0 = (float)(ind >> 8);
    const float* regb = reg + (long)b * 2 * HW;
    const float* whb  = wh  + (long)b * 2 * HW;
    float xs = x0 + regb[ind];
    float ys = y0 + regb[HW + ind];
    float w = whb[ind];
    float h = whb[HW + ind];
    float l  = xs - w * 0.5f;
    float t  = ys - h * 0.5f;
    float r  = xs + w * 0.5f;
    float bo = ys + h * 0.5f;
    g_bboxes[b][k][0] = l; g_bboxes[b][k][1] = t;
    g_bboxes[b][k][2] = r; g_bboxes[b][k][3] = bo;
    float* dr = det + (long)(b * KK + k) * 40;
    dr[0] = l; dr[1] = t; dr[2] = r; dr[3] = bo;
    dr[4] = score;
    dr[39] = 0.0f;   // clses (c=1 -> always 0)
}

// ---------------- keypoint assignment (cols 5..38) ----------------
__global__ void joints_kernel(const float* __restrict__ hps, const float* __restrict__ hp_offset,
                              float* __restrict__ det) {
    int j = blockIdx.x;
    int b = blockIdx.y;
    __shared__ float hx[KK], hy[KK], hs[KK];
    int t = threadIdx.x;
    if (t < KK) {
        int hi = g_hm_inds[b][j][t];
        float s = g_hm_scores[b][j][t];
        const float* hob = hp_offset + (long)b * 2 * HW;
        float ox = hob[hi];
        float oy = hob[HW + hi];
        bool m = s > THRESH_F;
        hs[t] = m ? s : -1.0f;
        hx[t] = m ? ((float)(hi & (WW - 1)) + ox) : -10000.0f;
        hy[t] = m ? ((float)(hi >> 8) + oy)       : -10000.0f;
    }
    __syncthreads();
    int k = t;
    if (k >= KK) return;

    int ind = g_top_inds[b][k];
    float x0 = (float)(ind & (WW - 1));
    float y0 = (float)(ind >> 8);
    const float* hpsb = hps + (long)b * (2 * JJ * HW);
    float kx = hpsb[(2 * j) * HW + ind] + x0;
    float ky = hpsb[(2 * j + 1) * HW + ind] + y0;

    // min over the 100 hm candidates (first-occurrence argmin, like jnp.argmin)
    float md = 1e30f; int am = 0;
    #pragma unroll 4
    for (int m_ = 0; m_ < KK; m_++) {
        float dx = kx - hx[m_];
        float dy = ky - hy[m_];
        float d = sqrtf(dx * dx + dy * dy);
        if (d < md) { md = d; am = m_; }
    }
    float g   = hs[am];
    float hkx = hx[am];
    float hky = hy[am];
    float l  = g_bboxes[b][k][0];
    float tt = g_bboxes[b][k][1];
    float r  = g_bboxes[b][k][2];
    float bo = g_bboxes[b][k][3];
    bool bad = (hkx < l) || (hkx > r) || (hky < tt) || (hky > bo)
            || (g < THRESH_F) || (md > fmaxf(bo - tt, r - l) * 0.3f);
    float outx = bad ? kx : hkx;
    float outy = bad ? ky : hky;
    float* dr = det + (long)(b * KK + k) * 40;
    dr[5 + 2 * j] = outx;
    dr[6 + 2 * j] = outy;
}

// ---------------- launch ----------------
extern "C" void kernel_launch(void* const* d_in, const int* in_sizes, int n_in,
                              void* d_out, int out_size) {
    const float* hm        = (const float*)d_in[0];
    const float* wh        = (const float*)d_in[1];
    const float* hps       = (const float*)d_in[2];
    const float* reg       = (const float*)d_in[3];
    const float* hm_hp     = (const float*)d_in[4];
    const float* hp_offset = (const float*)d_in[5];
    float* out = (float*)d_out;

    long o0 = 0;
    long o1 = o0 + in_sizes[0];   // wh
    long o2 = o1 + in_sizes[1];   // hps
    long o3 = o2 + in_sizes[2];   // reg
    long o4 = o3 + in_sizes[3];   // hm_hp
    long o5 = o4 + in_sizes[4];   // hp_offset
    long o6 = o5 + in_sizes[5];   // detections

    // sigmoids into their output regions
    {
        int n4 = in_sizes[0] / 4;
        sigmoid_kernel<<<(n4 + 255) / 256, 256>>>((const float4*)hm, (float4*)(out + o0), n4);
    }
    {
        int n4 = in_sizes[4] / 4;
        sigmoid_kernel<<<(n4 + 255) / 256, 256>>>((const float4*)hm_hp, (float4*)(out + o4), n4);
    }

    // pass-throughs (async D2D, graph-capturable)
    cudaMemcpyAsync(out + o1, wh,        (size_t)in_sizes[1] * sizeof(float), cudaMemcpyDeviceToDevice);
    cudaMemcpyAsync(out + o2, hps,       (size_t)in_sizes[2] * sizeof(float), cudaMemcpyDeviceToDevice);
    cudaMemcpyAsync(out + o3, reg,       (size_t)in_sizes[3] * sizeof(float), cudaMemcpyDeviceToDevice);
    cudaMemcpyAsync(out + o5, hp_offset, (size_t)in_sizes[5] * sizeof(float), cudaMemcpyDeviceToDevice);

    // top-K over all 144 channels (reads sigmoid outputs)
    cudaFuncSetAttribute(topk_kernel, cudaFuncAttributeMaxDynamicSharedMemorySize, MAXC * 8);
    topk_kernel<<<BB + BB * JJ, 1024, MAXC * 8>>>(out + o0, out + o4);

    // decode
    bbox_kernel<<<BB, 128>>>(reg, wh, out + o6);
    joints_kernel<<<dim3(JJ, BB), 128>>>(hps, hp_offset, out + o6);
}

// round 3
// speedup vs baseline: 3.2371x; 3.2371x over previous
#include <cuda_runtime.h>
#include <math.h>
#include <limits.h>

#define BB 8
#define HH 256
#define WW 256
#define KK 100
#define JJ 17
#define HW (HH*WW)
#define MAXC 16384
#define MSEL 512
#define TPB 1024
#define THRESH_F 0.1f
#define NEGBIG (-1e30f)

// ---------------- scratch (device globals) ----------------
__device__ float g_top_scores[BB][KK];
__device__ int   g_top_inds[BB][KK];
__device__ float g_hm_scores[BB][JJ][KK];
__device__ int   g_hm_inds[BB][JJ][KK];
__device__ float g_bboxes[BB][KK][4];

// ---------------- fused elementwise: sigmoid(hm), copies, sigmoid(hm_hp) ----------------
__global__ void elementwise_kernel(const float4* __restrict__ hm, const float4* __restrict__ wh,
                                   const float4* __restrict__ hps, const float4* __restrict__ reg,
                                   const float4* __restrict__ hmhp, const float4* __restrict__ hpo,
                                   float4* __restrict__ out,
                                   int e1, int e2, int e3, int e4, int e5, int e6) {
    int i = blockIdx.x * blockDim.x + threadIdx.x;
    if (i >= e6) return;
    float4 v; bool sg = false;
    if (i < e1)      { v = hm[i];        sg = true; }
    else if (i < e2) { v = wh[i - e1]; }
    else if (i < e3) { v = hps[i - e2]; }
    else if (i < e4) { v = reg[i - e3]; }
    else if (i < e5) { v = hmhp[i - e4]; sg = true; }
    else             { v = hpo[i - e5]; }
    if (sg) {
        v.x = 1.0f / (1.0f + expf(-v.x));
        v.y = 1.0f / (1.0f + expf(-v.y));
        v.z = 1.0f / (1.0f + expf(-v.z));
        v.w = 1.0f / (1.0f + expf(-v.w));
    }
    out[i] = v;
}

// ---------------- fused NMS + exact top-K (radix select) per channel ----------------
// Block ch < BB: hm channel (batch ch) + bbox tail. Block ch >= BB: hm_hp channel e=ch-BB (b*JJ+j).
__global__ void __launch_bounds__(TPB, 1)
topk_kernel(const float* __restrict__ out_hm, const float* __restrict__ out_hmhp,
            const float* __restrict__ reg, const float* __restrict__ wh,
            float* __restrict__ det) {
    extern __shared__ char smem_raw[];
    float* cvals = (float*)smem_raw;          // MAXC
    int*   cinds = (int*)(cvals + MAXC);      // MAXC
    __shared__ int s_count;
    __shared__ int hist[8][256];
    __shared__ int wtot[8];
    __shared__ unsigned s_selk[MSEL];
    __shared__ int s_seli[MSEL];
    __shared__ int s_m;
    __shared__ int s_bin, s_nh;

    const int ch = blockIdx.x;
    const int tid = threadIdx.x;
    const int lane = tid & 31;
    const float* src = (ch < BB) ? (out_hm + (long)ch * HW)
                                 : (out_hmhp + (long)(ch - BB) * HW);
    const float4* src4 = (const float4*)src;

    if (tid == 0) s_count = 0;
    __syncthreads();

    // ---- Phase 1: 3x3 NMS (>=, -inf padding) with float4, warp-aggregated push ----
    for (int i = tid; i < HW / 4; i += TPB) {
        int p = i << 2;
        int y = p >> 8;
        int x = p & 255;
        float4 c4 = src4[i];
        float L = (x > 0)   ? src[p - 1] : NEGBIG;
        float R = (x < 252) ? src[p + 4] : NEGBIG;
        float4 u4, d4; float uL, uR, dL, dR;
        if (y > 0) {
            u4 = src4[i - 64];
            uL = (x > 0)   ? src[p - 257] : NEGBIG;
            uR = (x < 252) ? src[p - 252] : NEGBIG;
        } else { u4 = make_float4(NEGBIG,NEGBIG,NEGBIG,NEGBIG); uL = uR = NEGBIG; }
        if (y < 255) {
            d4 = src4[i + 64];
            dL = (x > 0)   ? src[p + 255] : NEGBIG;
            dR = (x < 252) ? src[p + 260] : NEGBIG;
        } else { d4 = make_float4(NEGBIG,NEGBIG,NEGBIG,NEGBIG); dL = dR = NEGBIG; }

        bool m0 = c4.x >= uL   && c4.x >= u4.x && c4.x >= u4.y &&
                  c4.x >= L    && c4.x >= c4.y &&
                  c4.x >= dL   && c4.x >= d4.x && c4.x >= d4.y;
        bool m1 = c4.y >= u4.x && c4.y >= u4.y && c4.y >= u4.z &&
                  c4.y >= c4.x && c4.y >= c4.z &&
                  c4.y >= d4.x && c4.y >= d4.y && c4.y >= d4.z;
        bool m2 = c4.z >= u4.y && c4.z >= u4.z && c4.z >= u4.w &&
                  c4.z >= c4.y && c4.z >= c4.w &&
                  c4.z >= d4.y && c4.z >= d4.z && c4.z >= d4.w;
        bool m3 = c4.w >= u4.z && c4.w >= u4.w && c4.w >= uR &&
                  c4.w >= c4.z && c4.w >= R    &&
                  c4.w >= d4.z && c4.w >= d4.w && c4.w >= dR;

        bool  ms[4] = {m0, m1, m2, m3};
        float vs[4] = {c4.x, c4.y, c4.z, c4.w};
        #pragma unroll
        for (int s = 0; s < 4; s++) {
            unsigned ball = __ballot_sync(0xffffffffu, ms[s]);
            if (ball) {
                int leader = __ffs(ball) - 1;
                int base = 0;
                if (lane == leader) base = atomicAdd(&s_count, __popc(ball));
                base = __shfl_sync(0xffffffffu, base, leader);
                if (ms[s]) {
                    int pos = base + __popc(ball & ((1u << lane) - 1u));
                    if (pos < MAXC) { cvals[pos] = vs[s]; cinds[pos] = p + s; }
                }
            }
        }
    }
    __syncthreads();
    int count = min(s_count, MAXC);

    // ---- Phase 2: exact 100th-largest via 4-round MSB radix select ----
    // All values are sigmoid outputs in (0,1): positive -> uint bits are order-isomorphic.
    unsigned prefix = 0;
    int n_higher = 0;
    for (int round = 0; round < 4; round++) {
        int shift = 24 - 8 * round;
        for (int h = tid; h < 8 * 256; h += TPB) ((int*)hist)[h] = 0;
        if (tid == 0) { s_bin = 0; s_nh = n_higher; }
        __syncthreads();
        int w8 = (tid >> 5) & 7;
        for (int c = tid; c < count; c += TPB) {
            unsigned key = __float_as_uint(cvals[c]);
            bool inr = (round == 0) || ((key >> (shift + 8)) == prefix);
            if (inr) atomicAdd(&hist[w8][(key >> shift) & 255], 1);
        }
        __syncthreads();
        // reverse exclusive scan over 256 bins (8 warps), find crossing bin
        if (tid < 256) {
            int cbin = 0;
            #pragma unroll
            for (int w = 0; w < 8; w++) cbin += hist[w][tid];
            int suf = cbin;  // inclusive suffix within warp
            #pragma unroll
            for (int off = 1; off < 32; off <<= 1) {
                int v = __shfl_down_sync(0xffffffffu, suf, off);
                if (lane + off < 32) suf += v;
            }
            int wid = tid >> 5;
            if (lane == 0) wtot[wid] = suf;
            __syncwarp();
            // need all warp totals -> sync below
            hist[0][tid] = cbin;        // stash combined count
            hist[1][tid] = suf - cbin;  // stash warp-local exclusive suffix
        }
        __syncthreads();
        if (tid < 256) {
            int wid = tid >> 5;
            int hsum = 0;
            #pragma unroll
            for (int w = 0; w < 8; w++) if (w > wid) hsum += wtot[w];
            int cbin  = hist[0][tid];
            int sexcl = hist[1][tid] + hsum;      // # keys in bins strictly above tid
            int acc = n_higher + sexcl;
            if (acc < KK && acc + cbin >= KK) { s_bin = tid; s_nh = acc; }
        }
        __syncthreads();
        prefix = (prefix << 8) | (unsigned)s_bin;
        n_higher = s_nh;
        __syncthreads();
    }
    unsigned pivot = (count <= KK) ? 0u : prefix;

    // ---- Phase 3: collect >= pivot, exact rank, write ----
    if (tid == 0) s_m = 0;
    __syncthreads();
    for (int c = tid; c < count; c += TPB) {
        unsigned key = __float_as_uint(cvals[c]);
        if (key >= pivot) {
            int pos = atomicAdd(&s_m, 1);
            if (pos < MSEL) { s_selk[pos] = key; s_seli[pos] = cinds[c]; }
        }
    }
    __syncthreads();
    int M = min(s_m, MSEL);

    int e = ch - BB;
    // defaults (pad when fewer than KK)
    if (tid < KK) {
        if (ch < BB) { g_top_scores[ch][tid] = 0.0f; g_top_inds[ch][tid] = 0; }
        else         { g_hm_scores[e / JJ][e % JJ][tid] = 0.0f; g_hm_inds[e / JJ][e % JJ][tid] = 0; }
    }
    __syncthreads();

    for (int i = tid; i < M; i += TPB) {
        unsigned ki = s_selk[i]; int ii = s_seli[i];
        int rank = 0;
        for (int j = 0; j < M; j++) {
            unsigned kj = s_selk[j]; int ij = s_seli[j];
            rank += (kj > ki || (kj == ki && ij < ii)) ? 1 : 0;
        }
        if (rank < KK) {
            float v = __uint_as_float(ki);
            if (ch < BB) { g_top_scores[ch][rank] = v; g_top_inds[ch][rank] = ii; }
            else         { g_hm_scores[e / JJ][e % JJ][rank] = v; g_hm_inds[e / JJ][e % JJ][rank] = ii; }
        }
    }
    __syncthreads();

    // ---- bbox tail (hm blocks only): cols 0..4, 39 + g_bboxes ----
    if (ch < BB && tid < KK) {
        int b = ch, k = tid;
        int ind = g_top_inds[b][k];
        float score = g_top_scores[b][k];
        float x0 = (float)(ind & (WW - 1));
        float y0 = (float)(ind >> 8);
        const float* regb = reg + (long)b * 2 * HW;
        const float* whb  = wh  + (long)b * 2 * HW;
        float xs = x0 + regb[ind];
        float ys = y0 + regb[HW + ind];
        float w = whb[ind];
        float h = whb[HW + ind];
        float l  = xs - w * 0.5f;
        float t  = ys - h * 0.5f;
        float r  = xs + w * 0.5f;
        float bo = ys + h * 0.5f;
        g_bboxes[b][k][0] = l; g_bboxes[b][k][1] = t;
        g_bboxes[b][k][2] = r; g_bboxes[b][k][3] = bo;
        float* dr = det + (long)(b * KK + k) * 40;
        dr[0] = l; dr[1] = t; dr[2] = r; dr[3] = bo;
        dr[4] = score;
        dr[39] = 0.0f;
    }
}

// ---------------- keypoint assignment (cols 5..38) ----------------
__global__ void joints_kernel(const float* __restrict__ hps, const float* __restrict__ hp_offset,
                              float* __restrict__ det) {
    int j = blockIdx.x;
    int b = blockIdx.y;
    __shared__ float hx[KK], hy[KK], hs[KK];
    int t = threadIdx.x;
    if (t < KK) {
        int hi = g_hm_inds[b][j][t];
        float s = g_hm_scores[b][j][t];
        const float* hob = hp_offset + (long)b * 2 * HW;
        float ox = hob[hi];
        float oy = hob[HW + hi];
        bool m = s > THRESH_F;
        hs[t] = m ? s : -1.0f;
        hx[t] = m ? ((float)(hi & (WW - 1)) + ox) : -10000.0f;
        hy[t] = m ? ((float)(hi >> 8) + oy)       : -10000.0f;
    }
    __syncthreads();
    int k = t;
    if (k >= KK) return;

    int ind = g_top_inds[b][k];
    float x0 = (float)(ind & (WW - 1));
    float y0 = (float)(ind >> 8);
    const float* hpsb = hps + (long)b * (2 * JJ * HW);
    float kx = hpsb[(2 * j) * HW + ind] + x0;
    float ky = hpsb[(2 * j + 1) * HW + ind] + y0;

    float md = 1e30f; int am = 0;
    #pragma unroll 4
    for (int m_ = 0; m_ < KK; m_++) {
        float dx = kx - hx[m_];
        float dy = ky - hy[m_];
        float d = sqrtf(dx * dx + dy * dy);
        if (d < md) { md = d; am = m_; }
    }
    float g   = hs[am];
    float hkx = hx[am];
    float hky = hy[am];
    float l  = g_bboxes[b][k][0];
    float tt = g_bboxes[b][k][1];
    float r  = g_bboxes[b][k][2];
    float bo = g_bboxes[b][k][3];
    bool bad = (hkx < l) || (hkx > r) || (hky < tt) || (hky > bo)
            || (g < THRESH_F) || (md > fmaxf(bo - tt, r - l) * 0.3f);
    float outx = bad ? kx : hkx;
    float outy = bad ? ky : hky;
    float* dr = det + (long)(b * KK + k) * 40;
    dr[5 + 2 * j] = outx;
    dr[6 + 2 * j] = outy;
}

// ---------------- launch ----------------
extern "C" void kernel_launch(void* const* d_in, const int* in_sizes, int n_in,
                              void* d_out, int out_size) {
    const float* hm        = (const float*)d_in[0];
    const float* wh        = (const float*)d_in[1];
    const float* hps       = (const float*)d_in[2];
    const float* reg       = (const float*)d_in[3];
    const float* hm_hp     = (const float*)d_in[4];
    const float* hp_offset = (const float*)d_in[5];
    float* out = (float*)d_out;

    long o0 = 0;
    long o1 = o0 + in_sizes[0];
    long o2 = o1 + in_sizes[1];
    long o3 = o2 + in_sizes[2];
    long o4 = o3 + in_sizes[3];
    long o5 = o4 + in_sizes[4];
    long o6 = o5 + in_sizes[5];

    int e1 = (int)(o1 / 4), e2 = (int)(o2 / 4), e3 = (int)(o3 / 4),
        e4 = (int)(o4 / 4), e5 = (int)(o5 / 4), e6 = (int)(o6 / 4);

    elementwise_kernel<<<(e6 + 255) / 256, 256>>>(
        (const float4*)hm, (const float4*)wh, (const float4*)hps,
        (const float4*)reg, (const float4*)hm_hp, (const float4*)hp_offset,
        (float4*)out, e1, e2, e3, e4, e5, e6);

    cudaFuncSetAttribute(topk_kernel, cudaFuncAttributeMaxDynamicSharedMemorySize, MAXC * 8);
    topk_kernel<<<BB + BB * JJ, TPB, MAXC * 8>>>(out + o0, out + o4, reg, wh, out + o6);

    joints_kernel<<<dim3(JJ, BB), 128>>>(hps, hp_offset, out + o6);
}